// round 15
// baseline (speedup 1.0000x reference)
#include <cuda_runtime.h>
#include <cuda_bf16.h>

#define BB 16
#define LL 8400
#define NG 32
#define KK 68
#define NTOPK 13
#define EPSV 1e-9f
#define CAND_CAP 1024
#define SEL_CAP 640

// flat output offsets (float32 elements), tuple order:
// labels(B,L), bboxes(B,L,4), scores(B,L,1), poses(B,L,K,3), vertices(B,L,K,3),
// rotations(B,L,3,3), gt_index(B,L)
#define O1 134400
#define O2 672000
#define O3 806400
#define O4 28224000
#define O5 55641600
#define O6 56851200

// scratch (static __device__ globals — zero at load; self-cleaning across
// replays: k_cand re-zeroes g_mask, k_sel resets g_cnt, sel list overwritten)
__device__ unsigned int g_mask[BB * LL];        // raw claim bitmask per anchor
__device__ int          g_cnt[BB * NG];         // per-gt candidate count
__device__ float        g_cm[BB * NG * CAND_CAP];
__device__ int          g_ci[BB * NG * CAND_CAP];
__device__ int          g_selcnt[BB * NG];      // per-gt selection count (<=13)
__device__ int          g_sellist[BB * NG * NTOPK]; // local anchor ids

__device__ __forceinline__ float iou_fn(float gx1, float gy1, float gx2, float gy2,
                                        float px1, float py1, float px2, float py2) {
    float ix1 = fmaxf(gx1, px1), iy1 = fmaxf(gy1, py1);
    float ix2 = fminf(gx2, px2), iy2 = fminf(gy2, py2);
    float ov = fmaxf(ix2 - ix1, 0.f) * fmaxf(iy2 - iy1, 0.f);
    float a1 = fmaxf(gx2 - gx1, 0.f) * fmaxf(gy2 - gy1, 0.f);
    float a2 = fmaxf(px2 - px1, 0.f) * fmaxf(py2 - py1, 0.f);
    return ov / (a1 + a2 - ov + EPSV);
}

__device__ __forceinline__ bool in_gts_fn(float ax, float ay, float4 g) {
    return (ax - g.x > EPSV) && (ay - g.y > EPSV) && (g.z - ax > EPSV) && (g.w - ay > EPSV);
}

// ---------------- K_cand: zero mask + candidate building ----------------
__global__ void __launch_bounds__(128) k_cand(const float* __restrict__ ps,
                                              const float* __restrict__ pb,
                                              const float* __restrict__ ap,
                                              const float* __restrict__ gtb) {
    int b = blockIdx.y;
    int l = blockIdx.x * 128 + threadIdx.x;
    __shared__ float4 sg[NG];
    if (threadIdx.x < NG) sg[threadIdx.x] = ((const float4*)gtb)[b * NG + threadIdx.x];
    __syncthreads();
    bool act = (l < LL);
    int lane = threadIdx.x & 31;
    float ax = 0.f, ay = 0.f, sc = 0.f;
    float4 p = make_float4(0.f, 0.f, 0.f, 0.f);
    if (act) {
        g_mask[b * LL + l] = 0u;          // re-zero claims for this replay
        float2 apv = ((const float2*)ap)[l];
        ax = apv.x; ay = apv.y;
        int a = b * LL + l;
        p = ((const float4*)pb)[a];
        sc = ps[a];
    }
    for (int i = 0; i < NG; i++) {
        float4 g = sg[i];
        float m = 0.f;
        if (act && in_gts_fn(ax, ay, g)) {
            float iou = iou_fn(g.x, g.y, g.z, g.w, p.x, p.y, p.z, p.w);
            float i2 = iou * iou;
            m = sc * (i2 * i2 * i2);
        }
        unsigned want = __ballot_sync(0xffffffffu, m > 0.f);
        if (want) {
            int gid = b * NG + i;
            int leader = __ffs(want) - 1;
            int base = 0;
            if (lane == leader) base = atomicAdd(&g_cnt[gid], __popc(want));
            base = __shfl_sync(0xffffffffu, base, leader);
            if (m > 0.f) {
                int pos = base + __popc(want & ((1u << lane) - 1u));
                if (pos < CAND_CAP) {
                    g_cm[gid * CAND_CAP + pos] = m;
                    g_ci[gid * CAND_CAP + pos] = l;
                }
            }
        }
    }
}

// ---------------- K_sel: warp-per-gt top-13; claims + selection list ----------------
__global__ void __launch_bounds__(128) k_sel(const float* __restrict__ ap,
                                             const float* __restrict__ gtb,
                                             const float* __restrict__ pad) {
    __shared__ float sv[4][SEL_CAP];
    __shared__ int   si[4][SEL_CAP];
    int wl = threadIdx.x >> 5;
    int w  = blockIdx.x * 4 + wl;     // gt id: b*NG+gi
    int lane = threadIdx.x & 31;
    int b  = w >> 5;                  // NG == 32
    int gi = w & 31;
    int p = min(g_cnt[w], SEL_CAP);
    if (lane == 0) g_cnt[w] = 0;      // self-clean (all gts, incl. padded)
    if (pad[w] == 0.f) return;        // topk_mask==0; g_selcnt[w] stays 0
    int base = w * CAND_CAP;
    for (int j = lane; j < p; j += 32) { sv[wl][j] = g_cm[base + j]; si[wl][j] = g_ci[base + j]; }
    __syncwarp();
    unsigned mbase = b * LL;
    int nsel = min(p, NTOPK);
    int scnt = 0;
    for (int k = 0; k < nsel; k++) {
        float bv = -1.f; int bi = 1 << 30; int bj = -1;
        for (int j = lane; j < p; j += 32) {
            float v = sv[wl][j]; int idx = si[wl][j];
            if (v > bv || (v == bv && idx < bi)) { bv = v; bi = idx; bj = j; }
        }
        #pragma unroll
        for (int off = 16; off > 0; off >>= 1) {
            float ov = __shfl_down_sync(0xffffffffu, bv, off);
            int oi = __shfl_down_sync(0xffffffffu, bi, off);
            int oj = __shfl_down_sync(0xffffffffu, bj, off);
            if (ov > bv || (ov == bv && oi < bi)) { bv = ov; bi = oi; bj = oj; }
        }
        bj = __shfl_sync(0xffffffffu, bj, 0);
        bi = __shfl_sync(0xffffffffu, bi, 0);
        if (lane == 0) {
            sv[wl][bj] = -1.f;                        // remove selected
            atomicOr(&g_mask[mbase + bi], 1u << gi);  // candidates are in_gts by construction
            g_sellist[w * NTOPK + scnt] = bi;
        }
        scnt++;
    }
    // fill path: lax.top_k pads with lowest-index zero-value entries
    if (p < NTOPK) {
        int need = NTOPK - p;
        for (int l = 0; need > 0 && l < LL; l++) {
            bool ispos = false;
            for (int j = lane; j < p; j += 32) ispos |= (si[wl][j] == l);
            if (!__any_sync(0xffffffffu, ispos)) {
                need--;
                if (lane == 0) {
                    float2 apv = ((const float2*)ap)[l];
                    if (in_gts_fn(apv.x, apv.y, ((const float4*)gtb)[w])) {
                        atomicOr(&g_mask[mbase + l], 1u << gi);
                        g_sellist[w * NTOPK + scnt] = l;
                        scnt++;
                    }
                }
                scnt = __shfl_sync(0xffffffffu, scnt, 0);
            }
        }
    }
    if (lane == 0) g_selcnt[w] = scnt;   // overwritten deterministically each replay
}

// ---------------- K34: resolve + maxima + all outputs, warp-per-anchor ----------------
__global__ void __launch_bounds__(256) k34_out(
        const float* __restrict__ ps, const float* __restrict__ pb,
        const float* __restrict__ gtb, const float* __restrict__ gp,
        const float* __restrict__ gv, const float* __restrict__ grot,
        const int* __restrict__ gl, const int* __restrict__ bgp,
        float* __restrict__ out) {
    unsigned a = (blockIdx.x * 256u + threadIdx.x) >> 5;   // anchor = warp id
    int lane = threadIdx.x & 31;
    unsigned bits = g_mask[a];                 // raw claims (broadcast load)
    int b = a / LL;
    const float4* gtb4 = (const float4*)gtb + b * NG;

    int g = 0;            // resolved gt (0 for negatives: argmax of zero column)
    float score = 0.f;
    if (bits) {
        float4 pbox = ((const float4*)pb)[a];
        // lane-parallel iou vs gt 'lane'
        float4 gbl = __ldg(&gtb4[lane]);
        float iou_l = iou_fn(gbl.x, gbl.y, gbl.z, gbl.w, pbox.x, pbox.y, pbox.z, pbox.w);
        if (__popc(bits) > 1) {
            // argmax-iou over ALL 32 gts, first-index tiebreak
            float bv = iou_l; int bi = lane;
            #pragma unroll
            for (int off = 16; off > 0; off >>= 1) {
                float ov = __shfl_down_sync(0xffffffffu, bv, off);
                int oi = __shfl_down_sync(0xffffffffu, bi, off);
                if (ov > bv || (ov == bv && oi < bi)) { bv = ov; bi = oi; }
            }
            g = __shfl_sync(0xffffffffu, bi, 0);
        } else {
            g = __ffs(bits) - 1;
        }
        float myiou = __shfl_sync(0xffffffffu, iou_l, g);
        float4 gbox = __shfl_sync(0xffffffffu, gbl.x, g) == gbl.x ? gbl : gbl; // placeholder
        // gt g box for scan-iou: broadcast components from lane g
        float ggx = __shfl_sync(0xffffffffu, gbl.x, g);
        float ggy = __shfl_sync(0xffffffffu, gbl.y, g);
        float ggz = __shfl_sync(0xffffffffu, gbl.z, g);
        float ggw = __shfl_sync(0xffffffffu, gbl.w, g);
        // maxima over all anchors resolved to gt g: scan batch selection list
        float mx_m = 0.f, mx_iou = 0.f;
        for (int e = lane; e < NG * NTOPK; e += 32) {
            int gi2 = e / NTOPK, k = e % NTOPK;
            int gid2 = b * NG + gi2;
            if (k >= g_selcnt[gid2]) continue;
            int l2 = g_sellist[gid2 * NTOPK + k];
            int a2 = b * LL + l2;
            unsigned bt = g_mask[a2];
            int g2;
            float4 p2;
            bool havep2 = false;
            if (__popc(bt) > 1) {
                p2 = ((const float4*)pb)[a2]; havep2 = true;
                float bv = -1.f; int bq = 0;
                for (int j = 0; j < NG; j++) {
                    float4 gj = __ldg(&gtb4[j]);
                    float io = iou_fn(gj.x, gj.y, gj.z, gj.w, p2.x, p2.y, p2.z, p2.w);
                    if (io > bv) { bv = io; bq = j; }
                }
                g2 = bq;
            } else {
                g2 = __ffs(bt) - 1;
            }
            if (g2 == g) {
                if (!havep2) p2 = ((const float4*)pb)[a2];
                float io = iou_fn(ggx, ggy, ggz, ggw, p2.x, p2.y, p2.z, p2.w);
                float i2 = io * io;
                float m2 = ps[a2] * (i2 * i2 * i2);
                mx_m = fmaxf(mx_m, m2);
                mx_iou = fmaxf(mx_iou, io);
            }
        }
        #pragma unroll
        for (int off = 16; off > 0; off >>= 1) {
            mx_m = fmaxf(mx_m, __shfl_down_sync(0xffffffffu, mx_m, off));
            mx_iou = fmaxf(mx_iou, __shfl_down_sync(0xffffffffu, mx_iou, off));
        }
        if (lane == 0) {
            float i2 = myiou * myiou;
            float m = ps[a] * (i2 * i2 * i2);
            score = m / (mx_m + EPSV) * mx_iou;
        }
    }

    size_t gidx = (size_t)(b * NG + g);
    const float4* Psrc = (const float4*)gp + gidx * 51;
    const float4* Vsrc = (const float4*)gv + gidx * 51;
    float4* Pd = (float4*)(out + O3) + (size_t)a * 51;
    float4* Vd = (float4*)(out + O4) + (size_t)a * 51;

    int c0 = lane, c1 = lane + 32, c2 = lane + 64, c3 = lane + 96;
    float4 v0 = (c0 < 51) ? Psrc[c0] : Vsrc[c0 - 51];
    float4 v1 = (c1 < 51) ? Psrc[c1] : Vsrc[c1 - 51];
    float4 v2 = Vsrc[c2 - 51];
    float4 v3; bool has3 = (c3 < 102);
    float r9 = 0.f;
    if (has3) v3 = Vsrc[c3 - 51];
    if (lane < 9) r9 = grot[gidx * 9 + lane];

    if (c0 < 51) Pd[c0] = v0; else Vd[c0 - 51] = v0;
    if (c1 < 51) Pd[c1] = v1; else Vd[c1 - 51] = v1;
    Vd[c2 - 51] = v2;
    if (has3) Vd[c3 - 51] = v3;
    if (lane < 9) out[O5 + (size_t)a * 9 + lane] = r9;

    if (lane == 0) {
        int lbl = bits ? gl[gidx] : bgp[0];
        float4 gbox = ((const float4*)gtb)[gidx];
        float sc_out = (bits && lbl == 0) ? score : 0.f;  // one_hot(lbl, C+1)[..., keep=[0]]
        out[a] = (float)lbl;                // assigned_labels
        ((float4*)(out + O1))[a] = gbox;    // assigned_bboxes
        out[O2 + a] = sc_out;               // assigned_scores
        out[O6 + a] = (float)gidx;          // assigned_gt_index
    }
}

extern "C" void kernel_launch(void* const* d_in, const int* in_sizes, int n_in,
                              void* d_out, int out_size) {
    const float* ps  = (const float*)d_in[0];  // pred_scores  (B,L,1)
    const float* pb  = (const float*)d_in[1];  // pred_bboxes  (B,L,4)
    const float* ap  = (const float*)d_in[2];  // anchor_points(L,2)
    const int*   gl  = (const int*)  d_in[3];  // gt_labels
    const float* gtb = (const float*)d_in[4];  // gt_bboxes    (B,n,4)
    const float* gp  = (const float*)d_in[5];  // gt_poses     (B,n,K,3)
    const float* gv  = (const float*)d_in[6];  // gt_vertices  (B,n,K,3)
    const float* gr  = (const float*)d_in[7];  // gt_rotations (B,n,3,3)
    const float* pad = (const float*)d_in[8];  // pad_gt_mask  (B,n,1)
    const int*   bg  = (const int*)  d_in[9];  // bg_index scalar
    float* out = (float*)d_out;

    dim3 gc((LL + 127) / 128, BB);              // (66, 16) = 1056 blocks
    k_cand<<<gc, 128>>>(ps, pb, ap, gtb);
    k_sel<<<BB * NG / 4, 128>>>(ap, gtb, pad);
    // 134400 anchors = 134400 warps = 16800 blocks of 8 warps, exact
    k34_out<<<16800, 256>>>(ps, pb, gtb, gp, gv, gr, gl, bg, out);
}

// round 16
// speedup vs baseline: 2.1367x; 2.1367x over previous
#include <cuda_runtime.h>
#include <cuda_bf16.h>

#define BB 16
#define LL 8400
#define NG 32
#define KK 68
#define NTOPK 13
#define EPSV 1e-9f
#define CAND_CAP 1024
#define SEL_CAP 640

// flat output offsets (float32 elements), tuple order:
// labels(B,L), bboxes(B,L,4), scores(B,L,1), poses(B,L,K,3), vertices(B,L,K,3),
// rotations(B,L,3,3), gt_index(B,L)
#define O1 134400
#define O2 672000
#define O3 806400
#define O4 28224000
#define O5 55641600
#define O6 56851200

// scratch (static __device__ globals — zero at load; self-cleaning across
// graph replays: k_cand re-zeroes g_mask, k_sel resets g_cnt/g_maxm/g_maxiou)
__device__ unsigned int g_mask[BB * LL];   // claim bitmask; resolved in-place by k2
__device__ int          g_maxm[BB * NG];   // per-gt max metric (float bits, >=0)
__device__ int          g_maxiou[BB * NG]; // per-gt max iou    (float bits, >=0)
__device__ int          g_cnt[BB * NG];    // per-gt candidate count
__device__ float        g_cm[BB * NG * CAND_CAP]; // candidate metrics
__device__ int          g_ci[BB * NG * CAND_CAP]; // candidate anchor indices

__device__ __forceinline__ float iou_fn(float gx1, float gy1, float gx2, float gy2,
                                        float px1, float py1, float px2, float py2) {
    float ix1 = fmaxf(gx1, px1), iy1 = fmaxf(gy1, py1);
    float ix2 = fminf(gx2, px2), iy2 = fminf(gy2, py2);
    float ov = fmaxf(ix2 - ix1, 0.f) * fmaxf(iy2 - iy1, 0.f);
    float a1 = fmaxf(gx2 - gx1, 0.f) * fmaxf(gy2 - gy1, 0.f);
    float a2 = fmaxf(px2 - px1, 0.f) * fmaxf(py2 - py1, 0.f);
    return ov / (a1 + a2 - ov + EPSV);
}

__device__ __forceinline__ bool in_gts_fn(float ax, float ay, float4 g) {
    return (ax - g.x > EPSV) && (ay - g.y > EPSV) && (g.z - ax > EPSV) && (g.w - ay > EPSV);
}

// ---------------- K_cand: zero mask + anchor-keyed candidate building ----------------
// Reads each anchor once; appends (metric, l) to per-gt lists with
// warp-aggregated atomics. Candidate = in_gts && metric > 0.
__global__ void k_cand(const float* __restrict__ ps, const float* __restrict__ pb,
                       const float* __restrict__ ap, const float* __restrict__ gtb) {
    int b = blockIdx.y;
    int l = blockIdx.x * 256 + threadIdx.x;
    __shared__ float4 sg[NG];
    if (threadIdx.x < NG) sg[threadIdx.x] = ((const float4*)gtb)[b * NG + threadIdx.x];
    __syncthreads();
    bool act = (l < LL);
    int lane = threadIdx.x & 31;
    float ax = 0.f, ay = 0.f, sc = 0.f;
    float4 p = make_float4(0.f, 0.f, 0.f, 0.f);
    if (act) {
        g_mask[b * LL + l] = 0u;          // self-clean claims for this replay
        float2 apv = ((const float2*)ap)[l];
        ax = apv.x; ay = apv.y;
        int a = b * LL + l;
        p = ((const float4*)pb)[a];
        sc = ps[a];
    }
    for (int i = 0; i < NG; i++) {
        float4 g = sg[i];
        float m = 0.f;
        if (act && in_gts_fn(ax, ay, g)) {
            float iou = iou_fn(g.x, g.y, g.z, g.w, p.x, p.y, p.z, p.w);
            float i2 = iou * iou;
            m = sc * (i2 * i2 * i2);
        }
        unsigned want = __ballot_sync(0xffffffffu, m > 0.f);
        if (want) {
            int gid = b * NG + i;
            int leader = __ffs(want) - 1;
            int base = 0;
            if (lane == leader) base = atomicAdd(&g_cnt[gid], __popc(want));
            base = __shfl_sync(0xffffffffu, base, leader);
            if (m > 0.f) {
                int pos = base + __popc(want & ((1u << lane) - 1u));
                if (pos < CAND_CAP) {
                    g_cm[gid * CAND_CAP + pos] = m;
                    g_ci[gid * CAND_CAP + pos] = l;
                }
            }
        }
    }
}

// ---------------- K_sel: warp-per-gt top-13 over candidate list ----------------
__global__ void __launch_bounds__(128) k_sel(const float* __restrict__ ap,
                                             const float* __restrict__ gtb,
                                             const float* __restrict__ pad) {
    __shared__ float sv[4][SEL_CAP];
    __shared__ int   si[4][SEL_CAP];
    int wl = threadIdx.x >> 5;
    int w  = blockIdx.x * 4 + wl;     // gt id: b*NG+gi
    int lane = threadIdx.x & 31;
    int b  = w >> 5;                  // NG == 32
    int gi = w & 31;
    int p = min(g_cnt[w], SEL_CAP);
    if (lane == 0) {                  // self-clean (all gts, incl. padded)
        g_cnt[w] = 0;
        g_maxm[w] = 0;                // reset maxima before k2 atomicMax
        g_maxiou[w] = 0;
    }
    if (pad[w] == 0.f) return;        // topk_mask == 0 -> no claims from this gt
    int base = w * CAND_CAP;
    for (int j = lane; j < p; j += 32) { sv[wl][j] = g_cm[base + j]; si[wl][j] = g_ci[base + j]; }
    __syncwarp();
    unsigned mbase = b * LL;
    int nsel = min(p, NTOPK);
    for (int k = 0; k < nsel; k++) {
        float bv = -1.f; int bi = 1 << 30; int bj = -1;
        for (int j = lane; j < p; j += 32) {
            float v = sv[wl][j]; int idx = si[wl][j];
            if (v > bv || (v == bv && idx < bi)) { bv = v; bi = idx; bj = j; }
        }
        #pragma unroll
        for (int off = 16; off > 0; off >>= 1) {
            float ov = __shfl_down_sync(0xffffffffu, bv, off);
            int oi = __shfl_down_sync(0xffffffffu, bi, off);
            int oj = __shfl_down_sync(0xffffffffu, bj, off);
            if (ov > bv || (ov == bv && oi < bi)) { bv = ov; bi = oi; bj = oj; }
        }
        bj = __shfl_sync(0xffffffffu, bj, 0);
        bi = __shfl_sync(0xffffffffu, bi, 0);
        if (lane == 0) {
            sv[wl][bj] = -1.f;                        // remove selected
            atomicOr(&g_mask[mbase + bi], 1u << gi);  // candidates are in_gts by construction
        }
        __syncwarp();
    }
    // fill path: lax.top_k pads with lowest-index zero-value entries
    if (p < NTOPK && lane == 0) {
        float4 g = ((const float4*)gtb)[w];
        int need = NTOPK - p;
        for (int l = 0; need > 0 && l < LL; l++) {
            bool ispos = false;
            for (int j = 0; j < p; j++) if (si[wl][j] == l) { ispos = true; break; }
            if (!ispos) {
                need--;
                float2 apv = ((const float2*)ap)[l];
                if (in_gts_fn(apv.x, apv.y, g))
                    atomicOr(&g_mask[mbase + l], 1u << gi);
            }
        }
    }
}

// ---------------- K2: dense resolve (in-place) + per-gt maxima ----------------
// One anchor/thread; negatives exit after one load and store NOTHING.
__global__ void k2_resolve(const float* __restrict__ ps, const float* __restrict__ pb,
                           const float* __restrict__ gtb) {
    int b = blockIdx.y;
    int l = blockIdx.x * blockDim.x + threadIdx.x;
    __shared__ float4 sg[NG];
    if (threadIdx.x < NG) sg[threadIdx.x] = ((const float4*)gtb)[b * NG + threadIdx.x];
    __syncthreads();
    if (l >= LL) return;
    int a = b * LL + l;
    unsigned bits = g_mask[a];
    if (!bits) return;
    float4 p = ((const float4*)pb)[a];
    float sc = ps[a];
    int i;
    if (__popc(bits) > 1) {
        // replace column with one-hot argmax-iou over ALL gts (first-index tiebreak)
        float bv = -1.f; int bi = 0;
        #pragma unroll
        for (int j = 0; j < NG; j++) {
            float4 g = sg[j];
            float iou = iou_fn(g.x, g.y, g.z, g.w, p.x, p.y, p.z, p.w);
            if (iou > bv) { bv = iou; bi = j; }
        }
        i = bi;
        g_mask[a] = 1u << i;                 // in-place resolved one-hot
    } else {
        i = __ffs(bits) - 1;
    }
    float4 g = sg[i];
    float iou = iou_fn(g.x, g.y, g.z, g.w, p.x, p.y, p.z, p.w);
    float i2 = iou * iou;
    float m = sc * (i2 * i2 * i2);
    atomicMax(&g_maxm[b * NG + i], __float_as_int(m));     // >=0: int order == float order
    atomicMax(&g_maxiou[b * NG + i], __float_as_int(iou));
}

// ---------------- K34: warp-per-anchor, all outputs, streaming stores ----------------
__global__ void __launch_bounds__(256) k34_out(
        const float* __restrict__ ps, const float* __restrict__ pb,
        const float* __restrict__ gtb, const float* __restrict__ gp,
        const float* __restrict__ gv, const float* __restrict__ grot,
        const int* __restrict__ gl, const int* __restrict__ bgp,
        float* __restrict__ out) {
    unsigned a = (blockIdx.x * 256u + threadIdx.x) >> 5;   // anchor = warp id
    int lane = threadIdx.x & 31;
    unsigned bits = g_mask[a];                 // broadcast load (one-hot or 0)
    int b = a / LL;
    int i = bits ? (__ffs(bits) - 1) : 0;      // argmax of all-zero column = 0
    size_t gidx = (size_t)(b * NG + i);

    const float4* Psrc = (const float4*)gp + gidx * 51;
    const float4* Vsrc = (const float4*)gv + gidx * 51;
    float4* Pd = (float4*)(out + O3) + (size_t)a * 51;
    float4* Vd = (float4*)(out + O4) + (size_t)a * 51;

    int c0 = lane, c1 = lane + 32, c2 = lane + 64, c3 = lane + 96;
    float4 v0 = Psrc[c0];                      // c0 < 32 < 51 always
    float4 v1 = (c1 < 51) ? Psrc[c1] : Vsrc[c1 - 51];
    float4 v2 = Vsrc[c2 - 51];
    float4 v3; bool has3 = (c3 < 102);
    float r9 = 0.f;
    if (has3) v3 = Vsrc[c3 - 51];
    if (lane < 9) r9 = grot[gidx * 9 + lane];

    __stcs(&Pd[c0], v0);
    if (c1 < 51) __stcs(&Pd[c1], v1); else __stcs(&Vd[c1 - 51], v1);
    __stcs(&Vd[c2 - 51], v2);
    if (has3) __stcs(&Vd[c3 - 51], v3);
    if (lane < 9) __stcs(&out[O5 + (size_t)a * 9 + lane], r9);

    if (lane == 0) {
        int lbl = bits ? gl[gidx] : bgp[0];
        float4 gbox = ((const float4*)gtb)[gidx];
        float score = 0.f;
        if (bits) {
            float4 p = ((const float4*)pb)[a];
            float iou = iou_fn(gbox.x, gbox.y, gbox.z, gbox.w, p.x, p.y, p.z, p.w);
            float i2 = iou * iou;
            float m = ps[a] * (i2 * i2 * i2);
            float mm = __int_as_float(g_maxm[gidx]);
            float mi = __int_as_float(g_maxiou[gidx]);
            float am = m / (mm + EPSV) * mi;
            score = (lbl == 0) ? am : 0.f;  // one_hot(lbl, C+1)[..., keep=[0]]
        }
        __stcs(&out[a], (float)lbl);             // assigned_labels
        __stcs(&((float4*)(out + O1))[a], gbox); // assigned_bboxes
        __stcs(&out[O2 + a], score);             // assigned_scores
        __stcs(&out[O6 + a], (float)gidx);       // assigned_gt_index
    }
}

extern "C" void kernel_launch(void* const* d_in, const int* in_sizes, int n_in,
                              void* d_out, int out_size) {
    const float* ps  = (const float*)d_in[0];  // pred_scores  (B,L,1)
    const float* pb  = (const float*)d_in[1];  // pred_bboxes  (B,L,4)
    const float* ap  = (const float*)d_in[2];  // anchor_points(L,2)
    const int*   gl  = (const int*)  d_in[3];  // gt_labels
    const float* gtb = (const float*)d_in[4];  // gt_bboxes    (B,n,4)
    const float* gp  = (const float*)d_in[5];  // gt_poses     (B,n,K,3)
    const float* gv  = (const float*)d_in[6];  // gt_vertices  (B,n,K,3)
    const float* gr  = (const float*)d_in[7];  // gt_rotations (B,n,3,3)
    const float* pad = (const float*)d_in[8];  // pad_gt_mask  (B,n,1)
    const int*   bg  = (const int*)  d_in[9];  // bg_index scalar
    float* out = (float*)d_out;

    dim3 ga((LL + 255) / 256, BB);              // (33, 16) = 528 blocks
    k_cand<<<ga, 256>>>(ps, pb, ap, gtb);
    k_sel<<<BB * NG / 4, 128>>>(ap, gtb, pad);
    k2_resolve<<<ga, 256>>>(ps, pb, gtb);
    // 134400 anchors = 134400 warps = 16800 blocks of 8 warps, exact
    k34_out<<<16800, 256>>>(ps, pb, gtb, gp, gv, gr, gl, bg, out);
}

// round 17
// speedup vs baseline: 2.2638x; 1.0595x over previous
#include <cuda_runtime.h>
#include <cuda_bf16.h>

#define BB 16
#define LL 8400
#define NG 32
#define KK 68
#define NTOPK 13
#define EPSV 1e-9f
#define CAND_CAP 1024
#define SEL_CAP 640

// flat output offsets (float32 elements), tuple order:
// labels(B,L), bboxes(B,L,4), scores(B,L,1), poses(B,L,K,3), vertices(B,L,K,3),
// rotations(B,L,3,3), gt_index(B,L)
#define O1 134400
#define O2 672000
#define O3 806400
#define O4 28224000
#define O5 55641600
#define O6 56851200

// scratch (static __device__ globals — zero at load; self-cleaning across
// graph replays: k_cand re-zeroes g_mask, k_sel resets g_cnt/g_maxm/g_maxiou)
__device__ unsigned int g_mask[BB * LL];   // claim bitmask; resolved in-place by k2
__device__ int          g_maxm[BB * NG];   // per-gt max metric (float bits, >=0)
__device__ int          g_maxiou[BB * NG]; // per-gt max iou    (float bits, >=0)
__device__ int          g_cnt[BB * NG];    // per-gt candidate count
__device__ float        g_cm[BB * NG * CAND_CAP]; // candidate metrics
__device__ int          g_ci[BB * NG * CAND_CAP]; // candidate anchor indices

__device__ __forceinline__ float iou_fn(float gx1, float gy1, float gx2, float gy2,
                                        float px1, float py1, float px2, float py2) {
    float ix1 = fmaxf(gx1, px1), iy1 = fmaxf(gy1, py1);
    float ix2 = fminf(gx2, px2), iy2 = fminf(gy2, py2);
    float ov = fmaxf(ix2 - ix1, 0.f) * fmaxf(iy2 - iy1, 0.f);
    float a1 = fmaxf(gx2 - gx1, 0.f) * fmaxf(gy2 - gy1, 0.f);
    float a2 = fmaxf(px2 - px1, 0.f) * fmaxf(py2 - py1, 0.f);
    return ov / (a1 + a2 - ov + EPSV);
}

__device__ __forceinline__ bool in_gts_fn(float ax, float ay, float4 g) {
    return (ax - g.x > EPSV) && (ay - g.y > EPSV) && (g.z - ax > EPSV) && (g.w - ay > EPSV);
}

// ---------------- K_cand: zero mask + bitmask-then-sparse candidate building ----------------
// Cheap pass: 32-bit in_gts mask (4 compares/gt, no IoU, no ballot).
// Sparse pass: IoU + metric + per-thread atomic append only for set bits (~0.28/anchor).
__global__ void k_cand(const float* __restrict__ ps, const float* __restrict__ pb,
                       const float* __restrict__ ap, const float* __restrict__ gtb) {
    int b = blockIdx.y;
    int l = blockIdx.x * 256 + threadIdx.x;
    __shared__ float4 sg[NG];
    if (threadIdx.x < NG) sg[threadIdx.x] = ((const float4*)gtb)[b * NG + threadIdx.x];
    __syncthreads();
    if (l >= LL) return;                  // no warp collectives below — safe
    int a = b * LL + l;
    g_mask[a] = 0u;                       // self-clean claims for this replay
    float2 apv = ((const float2*)ap)[l];
    float ax = apv.x, ay = apv.y;

    unsigned inmask = 0u;
    #pragma unroll
    for (int i = 0; i < NG; i++)
        if (in_gts_fn(ax, ay, sg[i])) inmask |= (1u << i);
    if (!inmask) return;

    float4 p = ((const float4*)pb)[a];
    float sc = ps[a];
    while (inmask) {
        int i = __ffs(inmask) - 1;
        inmask &= inmask - 1u;
        float4 g = sg[i];
        float iou = iou_fn(g.x, g.y, g.z, g.w, p.x, p.y, p.z, p.w);
        float i2 = iou * iou;
        float m = sc * (i2 * i2 * i2);
        if (m > 0.f) {
            int gid = b * NG + i;
            int pos = atomicAdd(&g_cnt[gid], 1);
            if (pos < CAND_CAP) {
                g_cm[gid * CAND_CAP + pos] = m;
                g_ci[gid * CAND_CAP + pos] = l;
            }
        }
    }
}

// ---------------- K_sel: warp-per-gt top-13 over candidate list ----------------
__global__ void __launch_bounds__(128) k_sel(const float* __restrict__ ap,
                                             const float* __restrict__ gtb,
                                             const float* __restrict__ pad) {
    __shared__ float sv[4][SEL_CAP];
    __shared__ int   si[4][SEL_CAP];
    int wl = threadIdx.x >> 5;
    int w  = blockIdx.x * 4 + wl;     // gt id: b*NG+gi
    int lane = threadIdx.x & 31;
    int b  = w >> 5;                  // NG == 32
    int gi = w & 31;
    int p = min(g_cnt[w], SEL_CAP);
    if (lane == 0) {                  // self-clean (all gts, incl. padded)
        g_cnt[w] = 0;
        g_maxm[w] = 0;                // reset maxima before k2 atomicMax
        g_maxiou[w] = 0;
    }
    if (pad[w] == 0.f) return;        // topk_mask == 0 -> no claims from this gt
    int base = w * CAND_CAP;
    for (int j = lane; j < p; j += 32) { sv[wl][j] = g_cm[base + j]; si[wl][j] = g_ci[base + j]; }
    __syncwarp();
    unsigned mbase = b * LL;
    int nsel = min(p, NTOPK);
    for (int k = 0; k < nsel; k++) {
        float bv = -1.f; int bi = 1 << 30; int bj = -1;
        for (int j = lane; j < p; j += 32) {
            float v = sv[wl][j]; int idx = si[wl][j];
            if (v > bv || (v == bv && idx < bi)) { bv = v; bi = idx; bj = j; }
        }
        #pragma unroll
        for (int off = 16; off > 0; off >>= 1) {
            float ov = __shfl_down_sync(0xffffffffu, bv, off);
            int oi = __shfl_down_sync(0xffffffffu, bi, off);
            int oj = __shfl_down_sync(0xffffffffu, bj, off);
            if (ov > bv || (ov == bv && oi < bi)) { bv = ov; bi = oi; bj = oj; }
        }
        bj = __shfl_sync(0xffffffffu, bj, 0);
        bi = __shfl_sync(0xffffffffu, bi, 0);
        if (lane == 0) {
            sv[wl][bj] = -1.f;                        // remove selected
            atomicOr(&g_mask[mbase + bi], 1u << gi);  // candidates are in_gts by construction
        }
        __syncwarp();
    }
    // fill path: lax.top_k pads with lowest-index zero-value entries
    if (p < NTOPK && lane == 0) {
        float4 g = ((const float4*)gtb)[w];
        int need = NTOPK - p;
        for (int l = 0; need > 0 && l < LL; l++) {
            bool ispos = false;
            for (int j = 0; j < p; j++) if (si[wl][j] == l) { ispos = true; break; }
            if (!ispos) {
                need--;
                float2 apv = ((const float2*)ap)[l];
                if (in_gts_fn(apv.x, apv.y, g))
                    atomicOr(&g_mask[mbase + l], 1u << gi);
            }
        }
    }
}

// ---------------- K2: dense resolve (in-place) + per-gt maxima ----------------
// One anchor/thread; negatives exit after one load and store NOTHING.
__global__ void k2_resolve(const float* __restrict__ ps, const float* __restrict__ pb,
                           const float* __restrict__ gtb) {
    int b = blockIdx.y;
    int l = blockIdx.x * blockDim.x + threadIdx.x;
    __shared__ float4 sg[NG];
    if (threadIdx.x < NG) sg[threadIdx.x] = ((const float4*)gtb)[b * NG + threadIdx.x];
    __syncthreads();
    if (l >= LL) return;
    int a = b * LL + l;
    unsigned bits = g_mask[a];
    if (!bits) return;
    float4 p = ((const float4*)pb)[a];
    float sc = ps[a];
    int i;
    if (__popc(bits) > 1) {
        // replace column with one-hot argmax-iou over ALL gts (first-index tiebreak)
        float bv = -1.f; int bi = 0;
        #pragma unroll
        for (int j = 0; j < NG; j++) {
            float4 g = sg[j];
            float iou = iou_fn(g.x, g.y, g.z, g.w, p.x, p.y, p.z, p.w);
            if (iou > bv) { bv = iou; bi = j; }
        }
        i = bi;
        g_mask[a] = 1u << i;                 // in-place resolved one-hot
    } else {
        i = __ffs(bits) - 1;
    }
    float4 g = sg[i];
    float iou = iou_fn(g.x, g.y, g.z, g.w, p.x, p.y, p.z, p.w);
    float i2 = iou * iou;
    float m = sc * (i2 * i2 * i2);
    atomicMax(&g_maxm[b * NG + i], __float_as_int(m));     // >=0: int order == float order
    atomicMax(&g_maxiou[b * NG + i], __float_as_int(iou));
}

// ---------------- K34: warp-per-anchor, all outputs, streaming stores ----------------
__global__ void __launch_bounds__(256) k34_out(
        const float* __restrict__ ps, const float* __restrict__ pb,
        const float* __restrict__ gtb, const float* __restrict__ gp,
        const float* __restrict__ gv, const float* __restrict__ grot,
        const int* __restrict__ gl, const int* __restrict__ bgp,
        float* __restrict__ out) {
    unsigned a = (blockIdx.x * 256u + threadIdx.x) >> 5;   // anchor = warp id
    int lane = threadIdx.x & 31;
    unsigned bits = g_mask[a];                 // broadcast load (one-hot or 0)
    int b = a / LL;
    int i = bits ? (__ffs(bits) - 1) : 0;      // argmax of all-zero column = 0
    size_t gidx = (size_t)(b * NG + i);

    const float4* Psrc = (const float4*)gp + gidx * 51;
    const float4* Vsrc = (const float4*)gv + gidx * 51;
    float4* Pd = (float4*)(out + O3) + (size_t)a * 51;
    float4* Vd = (float4*)(out + O4) + (size_t)a * 51;

    int c0 = lane, c1 = lane + 32, c2 = lane + 64, c3 = lane + 96;
    float4 v0 = Psrc[c0];                      // c0 < 32 < 51 always
    float4 v1 = (c1 < 51) ? Psrc[c1] : Vsrc[c1 - 51];
    float4 v2 = Vsrc[c2 - 51];
    float4 v3; bool has3 = (c3 < 102);
    float r9 = 0.f;
    if (has3) v3 = Vsrc[c3 - 51];
    if (lane < 9) r9 = grot[gidx * 9 + lane];

    __stcs(&Pd[c0], v0);
    if (c1 < 51) __stcs(&Pd[c1], v1); else __stcs(&Vd[c1 - 51], v1);
    __stcs(&Vd[c2 - 51], v2);
    if (has3) __stcs(&Vd[c3 - 51], v3);
    if (lane < 9) __stcs(&out[O5 + (size_t)a * 9 + lane], r9);

    if (lane == 0) {
        int lbl = bits ? gl[gidx] : bgp[0];
        float4 gbox = ((const float4*)gtb)[gidx];
        float score = 0.f;
        if (bits) {
            float4 p = ((const float4*)pb)[a];
            float iou = iou_fn(gbox.x, gbox.y, gbox.z, gbox.w, p.x, p.y, p.z, p.w);
            float i2 = iou * iou;
            float m = ps[a] * (i2 * i2 * i2);
            float mm = __int_as_float(g_maxm[gidx]);
            float mi = __int_as_float(g_maxiou[gidx]);
            float am = m / (mm + EPSV) * mi;
            score = (lbl == 0) ? am : 0.f;  // one_hot(lbl, C+1)[..., keep=[0]]
        }
        __stcs(&out[a], (float)lbl);             // assigned_labels
        __stcs(&((float4*)(out + O1))[a], gbox); // assigned_bboxes
        __stcs(&out[O2 + a], score);             // assigned_scores
        __stcs(&out[O6 + a], (float)gidx);       // assigned_gt_index
    }
}

extern "C" void kernel_launch(void* const* d_in, const int* in_sizes, int n_in,
                              void* d_out, int out_size) {
    const float* ps  = (const float*)d_in[0];  // pred_scores  (B,L,1)
    const float* pb  = (const float*)d_in[1];  // pred_bboxes  (B,L,4)
    const float* ap  = (const float*)d_in[2];  // anchor_points(L,2)
    const int*   gl  = (const int*)  d_in[3];  // gt_labels
    const float* gtb = (const float*)d_in[4];  // gt_bboxes    (B,n,4)
    const float* gp  = (const float*)d_in[5];  // gt_poses     (B,n,K,3)
    const float* gv  = (const float*)d_in[6];  // gt_vertices  (B,n,K,3)
    const float* gr  = (const float*)d_in[7];  // gt_rotations (B,n,3,3)
    const float* pad = (const float*)d_in[8];  // pad_gt_mask  (B,n,1)
    const int*   bg  = (const int*)  d_in[9];  // bg_index scalar
    float* out = (float*)d_out;

    dim3 ga((LL + 255) / 256, BB);              // (33, 16) = 528 blocks
    k_cand<<<ga, 256>>>(ps, pb, ap, gtb);
    k_sel<<<BB * NG / 4, 128>>>(ap, gtb, pad);
    k2_resolve<<<ga, 256>>>(ps, pb, gtb);
    // 134400 anchors = 134400 warps = 16800 blocks of 8 warps, exact
    k34_out<<<16800, 256>>>(ps, pb, gtb, gp, gv, gr, gl, bg, out);
}